// round 6
// baseline (speedup 1.0000x reference)
#include <cuda_runtime.h>

// ---------------------------------------------------------------------------
// WT_series_decomp via composed filter banks.
// Analysis: x --(22-tap stride-4 C2)--> lo2(8197) --afb--> lo3(4102) --afb--> lo4(2054)
// Synthesis: lo4 --(4x up, P-phases)--> t2(8198) --(4x up, P-phases + x)--> out
// One CTA (512 thr) per row, ~57.5KB smem -> 4 CTAs/SM, single wave.
// ---------------------------------------------------------------------------

#define NT      512
#define N0      32768
#define NROWS   512
#define HALF    16777216

// smem layout (floats): A holds lo2 then t2; B holds lo3; C holds lo4.
#define A_FRONT 8
#define A_ALLOC (A_FRONT + 8204)    // lo2 0..8196 + zfill ..8203 ; t2 0..8197
#define B_FRONT 6
#define B_ALLOC (B_FRONT + 4108)    // lo3 0..4101 + zfill ..4107
#define C_ALLOC 2056                // lo4 0..2053 + zfill ..2055
#define SMEM_FLOATS (A_ALLOC + B_ALLOC + C_ALLOC)   // 14382
#define SMEM_BYTES  (SMEM_FLOATS * 4)               // 57528 -> 4 CTAs/SM

// DEC_LO
#define G0 (-0.010597401784997278f)
#define G1 ( 0.032883011666982945f)
#define G2 ( 0.030841381835986965f)
#define G3 (-0.18703481171888114f)
#define G4 (-0.02798376941698385f)
#define G5 ( 0.6308807679295904f)
#define G6 ( 0.7148465705525415f)
#define G7 ( 0.23037781330885523f)
// H[k] = DEC_LO[7-k]
#define H0 G7
#define H1 G6
#define H2 G5
#define H3 G4
#define H4 G3
#define H5 G2
#define H6 G1
#define H7 G0

// Composed 2-level analysis filter: C2[t] = sum_{j+2k=t} H[j]*H[k], t in [0,22)
#define C2_0  (H0*H0)
#define C2_1  (H1*H0)
#define C2_2  (H2*H0 + H0*H1)
#define C2_3  (H3*H0 + H1*H1)
#define C2_4  (H4*H0 + H2*H1 + H0*H2)
#define C2_5  (H5*H0 + H3*H1 + H1*H2)
#define C2_6  (H6*H0 + H4*H1 + H2*H2 + H0*H3)
#define C2_7  (H7*H0 + H5*H1 + H3*H2 + H1*H3)
#define C2_8  (H6*H1 + H4*H2 + H2*H3 + H0*H4)
#define C2_9  (H7*H1 + H5*H2 + H3*H3 + H1*H4)
#define C2_10 (H6*H2 + H4*H3 + H2*H4 + H0*H5)
#define C2_11 (H7*H2 + H5*H3 + H3*H4 + H1*H5)
#define C2_12 (H6*H3 + H4*H4 + H2*H5 + H0*H6)
#define C2_13 (H7*H3 + H5*H4 + H3*H5 + H1*H6)
#define C2_14 (H6*H4 + H4*H5 + H2*H6 + H0*H7)
#define C2_15 (H7*H4 + H5*H5 + H3*H6 + H1*H7)
#define C2_16 (H6*H5 + H4*H6 + H2*H7)
#define C2_17 (H7*H5 + H5*H6 + H3*H7)
#define C2_18 (H6*H6 + H4*H7)
#define C2_19 (H7*H6 + H5*H7)
#define C2_20 (H6*H7)
#define C2_21 (H7*H7)

// Composed 2-level synthesis polyphases: out[4a+r] = sum_d Pr[d]*in[a+d]
#define P0_0 (G1*G1 + G3*G0)
#define P0_1 (G1*G3 + G3*G2 + G5*G1 + G7*G0)
#define P0_2 (G1*G5 + G3*G4 + G5*G3 + G7*G2)
#define P0_3 (G1*G7 + G3*G6 + G5*G5 + G7*G4)
#define P0_4 (G5*G7 + G7*G6)
#define P1_0 (G0*G1 + G2*G0)
#define P1_1 (G0*G3 + G2*G2 + G4*G1 + G6*G0)
#define P1_2 (G0*G5 + G2*G4 + G4*G3 + G6*G2)
#define P1_3 (G0*G7 + G2*G6 + G4*G5 + G6*G4)
#define P1_4 (G4*G7 + G6*G6)
#define P2_0 (G1*G0)
#define P2_1 (G1*G2 + G3*G1 + G5*G0)
#define P2_2 (G1*G4 + G3*G3 + G5*G2 + G7*G1)
#define P2_3 (G1*G6 + G3*G5 + G5*G4 + G7*G3)
#define P2_4 (G3*G7 + G5*G6 + G7*G5)
#define P2_5 (G7*G7)
#define P3_0 (G0*G0)
#define P3_1 (G0*G2 + G2*G1 + G4*G0)
#define P3_2 (G0*G4 + G2*G3 + G4*G2 + G6*G1)
#define P3_3 (G0*G6 + G2*G5 + G4*G4 + G6*G3)
#define P3_4 (G2*G7 + G4*G6 + G6*G5)
#define P3_5 (G6*G7)

__device__ __forceinline__ float dot8(float2 a, float2 b, float2 c, float2 d) {
    float s = a.x * H0;
    s = fmaf(a.y, H1, s);
    s = fmaf(b.x, H2, s);
    s = fmaf(b.y, H3, s);
    s = fmaf(c.x, H4, s);
    s = fmaf(c.y, H5, s);
    s = fmaf(d.x, H6, s);
    s = fmaf(d.y, H7, s);
    return s;
}

// Fused 2-level analysis: lo2[o] = sum_t C2[t] * xe[4o-18+t], o in [0,8197).
// Fast path o in [5,8192); guarded path o in {0..4, 8192}; exact cascade for
// o in {8193..8196} (where lo1 clamping matters).
__device__ __forceinline__ void afb2_fused(const float* __restrict__ x,
                                           float* __restrict__ lo2, int tid) {
    for (int o = tid; o < 8197; o += NT) {
        float s;
        if (o >= 5 && o < 8192) {
            const float2* p = (const float2*)(x + 4 * o - 18);
            float2 v0 = p[0], v1 = p[1], v2 = p[2], v3 = p[3], v4 = p[4];
            float2 v5 = p[5], v6 = p[6], v7 = p[7], v8 = p[8], v9 = p[9];
            float2 v10 = p[10];
            s = v0.x * C2_0;
            s = fmaf(v0.y,  C2_1,  s);
            s = fmaf(v1.x,  C2_2,  s);
            s = fmaf(v1.y,  C2_3,  s);
            s = fmaf(v2.x,  C2_4,  s);
            s = fmaf(v2.y,  C2_5,  s);
            s = fmaf(v3.x,  C2_6,  s);
            s = fmaf(v3.y,  C2_7,  s);
            s = fmaf(v4.x,  C2_8,  s);
            s = fmaf(v4.y,  C2_9,  s);
            s = fmaf(v5.x,  C2_10, s);
            s = fmaf(v5.y,  C2_11, s);
            s = fmaf(v6.x,  C2_12, s);
            s = fmaf(v6.y,  C2_13, s);
            s = fmaf(v7.x,  C2_14, s);
            s = fmaf(v7.y,  C2_15, s);
            s = fmaf(v8.x,  C2_16, s);
            s = fmaf(v8.y,  C2_17, s);
            s = fmaf(v9.x,  C2_18, s);
            s = fmaf(v9.y,  C2_19, s);
            s = fmaf(v10.x, C2_20, s);
            s = fmaf(v10.y, C2_21, s);
        } else if (o <= 8192) {
            int base = 4 * o - 18;
            s = 0.0f;
#define CGUARD(t, coef) { int ix = base + (t); \
            float v = (ix >= 0 && ix < N0) ? x[ix] : 0.0f; s = fmaf(v, (coef), s); }
            CGUARD(0,  C2_0)  CGUARD(1,  C2_1)  CGUARD(2,  C2_2)  CGUARD(3,  C2_3)
            CGUARD(4,  C2_4)  CGUARD(5,  C2_5)  CGUARD(6,  C2_6)  CGUARD(7,  C2_7)
            CGUARD(8,  C2_8)  CGUARD(9,  C2_9)  CGUARD(10, C2_10) CGUARD(11, C2_11)
            CGUARD(12, C2_12) CGUARD(13, C2_13) CGUARD(14, C2_14) CGUARD(15, C2_15)
            CGUARD(16, C2_16) CGUARD(17, C2_17) CGUARD(18, C2_18) CGUARD(19, C2_19)
            CGUARD(20, C2_20) CGUARD(21, C2_21)
#undef CGUARD
        } else {
            // o in {8193..8196}: exact two-step with lo1 clamped at 16387
            const float Ht[8] = {H0, H1, H2, H3, H4, H5, H6, H7};
            s = 0.0f;
#pragma unroll
            for (int k = 0; k < 8; k++) {
                int m = 2 * o - 6 + k;
                if (m < 16387) {
                    int b2 = 2 * m - 6;
                    float inner = 0.0f;
#pragma unroll
                    for (int j = 0; j < 8; j++) {
                        int ix = b2 + j;
                        float v = (ix < N0) ? x[ix] : 0.0f;
                        inner = fmaf(v, Ht[j], inner);
                    }
                    s = fmaf(inner, Ht[k], s);
                }
            }
        }
        lo2[o] = s;
    }
    if (tid < 7) lo2[8197 + tid] = 0.0f;  // zero-fill for next afb stage
}

// Single-level analysis from smem, pairwise. n_out even. zf = zero-fill count.
__device__ __forceinline__ void afb(const float* __restrict__ in,
                                    float* __restrict__ out,
                                    int n_out, int zf, int tid) {
    const int npair = n_out >> 1;
    for (int m = tid; m < npair; m += NT) {
        const float2* p = (const float2*)(in + 4 * m - 6);
        float2 a = p[0], b = p[1], c = p[2], d = p[3], e = p[4];
        float s0 = dot8(a, b, c, d);
        float s1 = dot8(b, c, d, e);
        *(float2*)(out + 2 * m) = make_float2(s0, s1);
    }
    if (tid < zf) out[n_out + tid] = 0.0f;
}

// Composed 4x upsampler: 8 outputs (n = 8q..8q+7) from in[2q..2q+6].
__device__ __forceinline__ void up8_from(const float* __restrict__ in, int a2,
                                         float4& o03, float4& o47) {
    const float2* p = (const float2*)(in + a2);
    float2 w0 = p[0], w1 = p[1], w2 = p[2], w3 = p[3];
    float i0 = w0.x, i1 = w0.y, i2 = w1.x, i3 = w1.y;
    float i4 = w2.x, i5 = w2.y, i6 = w3.x;
    o03.x = fmaf(i0, P0_0, fmaf(i1, P0_1, fmaf(i2, P0_2, fmaf(i3, P0_3, i4 * P0_4))));
    o03.y = fmaf(i0, P1_0, fmaf(i1, P1_1, fmaf(i2, P1_2, fmaf(i3, P1_3, i4 * P1_4))));
    o03.z = fmaf(i0, P2_0, fmaf(i1, P2_1, fmaf(i2, P2_2, fmaf(i3, P2_3,
                 fmaf(i4, P2_4, i5 * P2_5)))));
    o03.w = fmaf(i0, P3_0, fmaf(i1, P3_1, fmaf(i2, P3_2, fmaf(i3, P3_3,
                 fmaf(i4, P3_4, i5 * P3_5)))));
    o47.x = fmaf(i1, P0_0, fmaf(i2, P0_1, fmaf(i3, P0_2, fmaf(i4, P0_3, i5 * P0_4))));
    o47.y = fmaf(i1, P1_0, fmaf(i2, P1_1, fmaf(i3, P1_2, fmaf(i4, P1_3, i5 * P1_4))));
    o47.z = fmaf(i1, P2_0, fmaf(i2, P2_1, fmaf(i3, P2_2, fmaf(i4, P2_3,
                 fmaf(i5, P2_4, i6 * P2_5)))));
    o47.w = fmaf(i1, P3_0, fmaf(i2, P3_1, fmaf(i3, P3_2, fmaf(i4, P3_3,
                 fmaf(i5, P3_4, i6 * P3_5)))));
}

__global__ void __launch_bounds__(NT, 4)
wt_kernel(const float* __restrict__ x, float* __restrict__ out) {
    extern __shared__ float sm[];
    float* A = sm + A_FRONT;                       // 16B aligned (A_FRONT=8)
    float* B = sm + A_ALLOC + B_FRONT;
    float* C = sm + A_ALLOC + B_ALLOC;

    const int tid = threadIdx.x;
    const int row = blockIdx.x;
    const float* xr = x + (size_t)row * N0;

    // Zero front margins (read by afb at m=0..1)
    if (tid < 8) A[tid - 8] = 0.0f;
    if (tid < 6) B[tid - 6] = 0.0f;

    // Fused analysis levels 1+2: x(global) -> lo2 (8197) in A
    afb2_fused(xr, A, tid);
    __syncthreads();

    // Level 3: lo2 -> lo3 (4102) in B ; Level 4: lo3 -> lo4 (2054) in C
    afb(A, B, 4102, 6, tid); __syncthreads();
    afb(B, C, 2054, 2, tid); __syncthreads();

    // Fused synthesis levels 4+3: lo4 -> t2 (8198) in A (lo2 dead)
    for (int q = tid; q < 1025; q += NT) {
        float4 a, b;
        up8_from(C, 2 * q, a, b);
        if (q < 1024) {
            *(float4*)(A + 8 * q)     = a;
            *(float4*)(A + 8 * q + 4) = b;
        } else {
            *(float4*)(A + 8192) = a;                       // t2[8192..8195]
            *(float2*)(A + 8196) = make_float2(b.x, b.y);   // t2[8196..8197]
        }
    }
    __syncthreads();

    // Fused synthesis levels 2+1 + season = x - trend, streamed to global.
    float* season = out + (size_t)row * N0;
    float* trend  = out + (size_t)HALF + (size_t)row * N0;
    const float4* x4 = (const float4*)xr;
    float4* s4p = (float4*)season;
    float4* t4p = (float4*)trend;

    for (int q = tid; q < 4096; q += NT) {
        float4 tlo, thi;
        up8_from(A, 2 * q, tlo, thi);
        float4 xa = x4[2 * q], xb = x4[2 * q + 1];
        t4p[2 * q]     = tlo;
        t4p[2 * q + 1] = thi;
        s4p[2 * q]     = make_float4(xa.x - tlo.x, xa.y - tlo.y,
                                     xa.z - tlo.z, xa.w - tlo.w);
        s4p[2 * q + 1] = make_float4(xb.x - thi.x, xb.y - thi.y,
                                     xb.z - thi.z, xb.w - thi.w);
    }
}

extern "C" void kernel_launch(void* const* d_in, const int* in_sizes, int n_in,
                              void* d_out, int out_size) {
    const float* x = (const float*)d_in[0];
    float* out = (float*)d_out;
    cudaFuncSetAttribute(wt_kernel, cudaFuncAttributeMaxDynamicSharedMemorySize,
                         SMEM_BYTES);
    wt_kernel<<<NROWS, NT, SMEM_BYTES>>>(x, out);
}

// round 7
// speedup vs baseline: 1.4066x; 1.4066x over previous
#include <cuda_runtime.h>

// ---------------------------------------------------------------------------
// WT_series_decomp: 4-level lowpass DWT analysis+synthesis, season = x - trend.
// Each row is split across 2 CTAs (left/right half) with halo recompute.
// 512 threads/CTA, 49.7KB smem -> 4 CTAs/SM. Grid = 1024.
//
// Right-half slice bases (global indices):
//   lo1:8134  lo2:4070  lo3:2038  lo4:1022  t1:2044  t2:4092  t3:8188
// ---------------------------------------------------------------------------

#define NT      512
#define N0      32768
#define NROWS   512
#define HALF    16777216

#define P1_ALLOC 8264
#define P2_ALLOC 4140
#define SMEM_FLOATS (8 + P1_ALLOC + 8 + P2_ALLOC)   // 12420
#define SMEM_BYTES  (SMEM_FLOATS * 4)               // 49680 -> 4 CTAs/SM

// DEC_LO
#define G0 (-0.010597401784997278f)
#define G1 ( 0.032883011666982945f)
#define G2 ( 0.030841381835986965f)
#define G3 (-0.18703481171888114f)
#define G4 (-0.02798376941698385f)
#define G5 ( 0.6308807679295904f)
#define G6 ( 0.7148465705525415f)
#define G7 ( 0.23037781330885523f)
// H[k] = DEC_LO[7-k]
#define H0 G7
#define H1 G6
#define H2 G5
#define H3 G4
#define H4 G3
#define H5 G2
#define H6 G1
#define H7 G0

__device__ __forceinline__ float dot8(float2 a, float2 b, float2 c, float2 d) {
    float s = a.x * H0;
    s = fmaf(a.y, H1, s);
    s = fmaf(b.x, H2, s);
    s = fmaf(b.y, H3, s);
    s = fmaf(c.x, H4, s);
    s = fmaf(c.y, H5, s);
    s = fmaf(d.x, H6, s);
    s = fmaf(d.y, H7, s);
    return s;
}

// Level-1 analysis from GLOBAL x. Pair p -> local outputs (2p, 2p+1),
// global output base o0g = o_gbase + 2p, x window [2*o0g-6, 2*o0g+3].
// Fast (unguarded) for p in [p_lo, p_hi).
__device__ __forceinline__ void afb_global(const float* __restrict__ x,
                                           float* __restrict__ out,
                                           int pairs, int n_valid, int o_gbase,
                                           int p_lo, int p_hi, int tid) {
    for (int p = tid; p < pairs; p += NT) {
        int xb = 2 * (o_gbase + 2 * p) - 6;
        float2 a, b, c, d, e;
        if (p >= p_lo && p < p_hi) {
            const float2* pp = (const float2*)(x + xb);
            a = pp[0]; b = pp[1]; c = pp[2]; d = pp[3]; e = pp[4];
        } else {
            float v[10];
#pragma unroll
            for (int k = 0; k < 10; ++k) {
                int ix = xb + k;
                v[k] = (ix >= 0 && ix < N0) ? x[ix] : 0.0f;
            }
            a = make_float2(v[0], v[1]); b = make_float2(v[2], v[3]);
            c = make_float2(v[4], v[5]); d = make_float2(v[6], v[7]);
            e = make_float2(v[8], v[9]);
        }
        float s0 = dot8(a, b, c, d);
        float s1 = dot8(b, c, d, e);
        int o = 2 * p;
        if (o + 1 < n_valid) *(float2*)(out + o) = make_float2(s0, s1);
        else                 out[o] = s0;
    }
}

// Analysis from smem. Pair p reads in[in_off + 4p .. +9] (in_off even).
__device__ __forceinline__ void afb_smem(const float* __restrict__ in,
                                         float* __restrict__ out,
                                         int pairs, int n_valid, int in_off,
                                         int tid) {
    for (int p = tid; p < pairs; p += NT) {
        const float2* pp = (const float2*)(in + in_off + 4 * p);
        float2 a = pp[0], b = pp[1], c = pp[2], d = pp[3], e = pp[4];
        float s0 = dot8(a, b, c, d);
        float s1 = dot8(b, c, d, e);
        int o = 2 * p;
        if (o + 1 < n_valid) *(float2*)(out + o) = make_float2(s0, s1);
        else                 out[o] = s0;
    }
}

// Synthesis quad: local outputs 4q..4q+3 (quad start even in global coords),
// reads in[soff + 2q .. +4] (soff even).
__device__ __forceinline__ void sfb_smem(const float* __restrict__ in,
                                         float* __restrict__ out,
                                         int quads, int soff, int tid) {
    for (int q = tid; q < quads; q += NT) {
        const float2* pp = (const float2*)(in + soff + 2 * q);
        float2 u = pp[0], v = pp[1];
        float  w = pp[2].x;
        float4 t;
        t.x = fmaf(u.x, G1, fmaf(u.y, G3, fmaf(v.x, G5, v.y * G7)));
        t.y = fmaf(u.x, G0, fmaf(u.y, G2, fmaf(v.x, G4, v.y * G6)));
        t.z = fmaf(u.y, G1, fmaf(v.x, G3, fmaf(v.y, G5, w * G7)));
        t.w = fmaf(u.y, G0, fmaf(v.x, G2, fmaf(v.y, G4, w * G6)));
        *(float4*)(out + 4 * q) = t;
    }
}

__global__ void __launch_bounds__(NT, 4)
wt_kernel(const float* __restrict__ x, float* __restrict__ out) {
    extern __shared__ float sm[];
    float* P1 = sm + 8;
    float* P2 = sm + 8 + P1_ALLOC + 8;

    const int tid = threadIdx.x;
    const int row = blockIdx.x >> 1;
    const int h   = blockIdx.x & 1;
    const float* xr = x + (size_t)row * N0;

    if (tid < 8) { P1[tid - 8] = 0.0f; P2[tid - 8] = 0.0f; }

    if (h == 0) {
        // ---- left half: all slice bases are 0, margins are the zero fronts
        afb_global(xr, P1, 4128, 8256, 0, 2, 4128, tid);            // lo1
        __syncthreads();
        afb_smem(P1, P2, 2064, 4128, -6, tid); __syncthreads();     // lo2
        afb_smem(P2, P1, 1032, 2064, -6, tid); __syncthreads();     // lo3
        afb_smem(P1, P2,  516, 1032, -6, tid); __syncthreads();     // lo4
        sfb_smem(P2, P1,  514, 0, tid); __syncthreads();            // t1
        sfb_smem(P1, P2, 1026, 0, tid); __syncthreads();            // t2
        sfb_smem(P2, P1, 2050, 0, tid); __syncthreads();            // t3
    } else {
        // ---- right half: slices with halo; zfill emulates beyond-end zeros
        afb_global(xr, P1, 4127, 8253, 8134, 0, 4125, tid);         // lo1
        if (tid < 11) P1[8253 + tid] = 0.0f;
        __syncthreads();
        afb_smem(P1, P2, 2064, 4127, 0, tid);                       // lo2
        if (tid < 9) P2[4127 + tid] = 0.0f;
        __syncthreads();
        afb_smem(P2, P1, 1032, 2064, 0, tid);                       // lo3
        if (tid < 8) P1[2064 + tid] = 0.0f;
        __syncthreads();
        afb_smem(P1, P2,  516, 1032, 0, tid); __syncthreads();      // lo4
        sfb_smem(P2, P1,  515, 0, tid); __syncthreads();            // t1
        sfb_smem(P1, P2, 1027, 2, tid); __syncthreads();            // t2
        sfb_smem(P2, P1, 2050, 2, tid); __syncthreads();            // t3
    }

    // ---- final upsample + season = x - trend, streamed to global
    const int goff = h << 14;                       // 0 or 16384
    const int soff = h ? 4 : 0;
    const float* t3 = P1;
    float* season = out + (size_t)row * N0 + goff;
    float* trend  = out + (size_t)HALF + (size_t)row * N0 + goff;
    const float4* x4 = (const float4*)(xr + goff);
    float4* s4p = (float4*)season;
    float4* t4p = (float4*)trend;

    for (int q = tid; q < 4096; q += NT) {
        const float2* pp = (const float2*)(t3 + soff + 2 * q);
        float2 u = pp[0], v = pp[1];
        float  w = pp[2].x;
        float4 t;
        t.x = fmaf(u.x, G1, fmaf(u.y, G3, fmaf(v.x, G5, v.y * G7)));
        t.y = fmaf(u.x, G0, fmaf(u.y, G2, fmaf(v.x, G4, v.y * G6)));
        t.z = fmaf(u.y, G1, fmaf(v.x, G3, fmaf(v.y, G5, w * G7)));
        t.w = fmaf(u.y, G0, fmaf(v.x, G2, fmaf(v.y, G4, w * G6)));
        float4 xv = x4[q];
        t4p[q] = t;
        s4p[q] = make_float4(xv.x - t.x, xv.y - t.y, xv.z - t.z, xv.w - t.w);
    }
}

extern "C" void kernel_launch(void* const* d_in, const int* in_sizes, int n_in,
                              void* d_out, int out_size) {
    const float* x = (const float*)d_in[0];
    float* out = (float*)d_out;
    cudaFuncSetAttribute(wt_kernel, cudaFuncAttributeMaxDynamicSharedMemorySize,
                         SMEM_BYTES);
    wt_kernel<<<2 * NROWS, NT, SMEM_BYTES>>>(x, out);
}